// round 16
// baseline (speedup 1.0000x reference)
#include <cuda_runtime.h>
#include <cuda_fp16.h>
#include <math.h>
#include <cstdint>

// ---------------------------------------------------------------------------
// FieldPredictionNetwork:  B=32768, G=512, H0=1024, H1=512, W=64, MODES=32, FD=128
// MLP GEMMs: mma.sync fp16, asymmetric 2-product (A single-level, B hi+lo).
// FFT: batch-axis radix-4 Stockham with packed f32x2 butterflies.
// mid/out: register-tiled, packed f32x2 complex MACs (pre-negated DFT tables).
// ---------------------------------------------------------------------------

#define NB 32768

typedef unsigned long long u64t;

// -------------------- scratch (device globals) ------------------------------
__device__ __half g_geomh[NB * 512];
__device__ __half g_Winh[1024 * 512],  g_Winl[1024 * 512];
__device__ __half g_Wh1h[512 * 1024],  g_Wh1l[512 * 1024];
__device__ __half g_Wh2h[64 * 512],    g_Wh2l[64 * 512];
__device__ __half g_h0h[NB * 1024];
__device__ __half g_h1h[NB * 512];
__device__ float  g_xr[NB * 64];
__device__ float2 g_bufA[NB * 64];
__device__ float2 g_bufB[NB * 64];
__device__ float2 g_Z[NB * 64];
__device__ float2 g_dftF[64 * 64];
__device__ float2 g_dftFn[64 * 64];   // (-s, c) of g_dftF
__device__ float2 g_dftI[64 * 64];
__device__ float2 g_dftIn[64 * 64];   // (-s, c) of g_dftI
__device__ float2 g_P[64];
__device__ float2 g_M[64];
__device__ float2 g_r4a[85 * 3];
__device__ float2 g_r4b[42 * 3];
__device__ float2 g_btw[32768];

// -------------------- packed f32x2 helpers ----------------------------------
__device__ __forceinline__ u64t pk2(float x, float y) {
    u64t r; asm("mov.b64 %0, {%1, %2};" : "=l"(r) : "f"(x), "f"(y)); return r;
}
__device__ __forceinline__ float2 u2f(u64t v) {
    float2 r; asm("mov.b64 {%0, %1}, %2;" : "=f"(r.x), "=f"(r.y) : "l"(v)); return r;
}
__device__ __forceinline__ u64t fma2(u64t a, u64t b, u64t c) {
    u64t d; asm("fma.rn.f32x2 %0, %1, %2, %3;" : "=l"(d) : "l"(a), "l"(b), "l"(c)); return d;
}
__device__ __forceinline__ u64t add2(u64t a, u64t b) {
    u64t d; asm("add.rn.f32x2 %0, %1, %2;" : "=l"(d) : "l"(a), "l"(b)); return d;
}
__device__ __forceinline__ u64t sub2(u64t a, u64t b) {
    u64t d; asm("sub.rn.f32x2 %0, %1, %2;" : "=l"(d) : "l"(a), "l"(b)); return d;
}

// -------------------- small PTX wrappers ------------------------------------
__device__ __forceinline__ uint32_t smem_u32(const void* p) {
    uint32_t a;
    asm("{ .reg .u64 t; cvta.to.shared.u64 t, %1; cvt.u32.u64 %0, t; }" : "=r"(a) : "l"(p));
    return a;
}
__device__ __forceinline__ void ldsm_x4(uint32_t* r, uint32_t a) {
    asm volatile("ldmatrix.sync.aligned.m8n8.x4.shared.b16 {%0,%1,%2,%3}, [%4];"
                 : "=r"(r[0]), "=r"(r[1]), "=r"(r[2]), "=r"(r[3]) : "r"(a));
}
__device__ __forceinline__ void mma16816(float* c, const uint32_t* a,
                                         uint32_t b0, uint32_t b1) {
    asm volatile("mma.sync.aligned.m16n8k16.row.col.f32.f16.f16.f32 "
                 "{%0,%1,%2,%3}, {%4,%5,%6,%7}, {%8,%9}, {%0,%1,%2,%3};"
                 : "+f"(c[0]), "+f"(c[1]), "+f"(c[2]), "+f"(c[3])
                 : "r"(a[0]), "r"(a[1]), "r"(a[2]), "r"(a[3]), "r"(b0), "r"(b1));
}
__device__ __forceinline__ void cp16(uint32_t dst, const void* src) {
    asm volatile("cp.async.cg.shared.global [%0], [%1], 16;" :: "r"(dst), "l"(src));
}
#define CP_COMMIT()  asm volatile("cp.async.commit_group;" ::: "memory")
#define CP_WAIT(n)   asm volatile("cp.async.wait_group %0;" :: "n"(n) : "memory")

#define SWOFF(r, cc) ((uint32_t)((r) * 64 + (((cc) ^ (((r) >> 1) & 3)) << 4)))

// -------------------- fp32 -> fp16 conversions ------------------------------
__global__ void split_geom(const float* __restrict__ src, int n4)
{
    int i = blockIdx.x * blockDim.x + threadIdx.x;
    if (i >= n4) return;
    float4 v = reinterpret_cast<const float4*>(src)[i];
    __half2 a, b;
    a.x = __float2half_rn(v.x); a.y = __float2half_rn(v.y);
    b.x = __float2half_rn(v.z); b.y = __float2half_rn(v.w);
    reinterpret_cast<__half2*>(g_geomh)[2 * i]     = a;
    reinterpret_cast<__half2*>(g_geomh)[2 * i + 1] = b;
}

template <int SEL>
__global__ void split_w(const float* __restrict__ srcA,
                        const float* __restrict__ srcB, int n4each)
{
    int blk = blockIdx.x;
    const float* src;
    __half *hi, *lo;
    int i;
    if (SEL == 0) {
        int half1 = gridDim.x / 2;
        if (blk < half1) { src = srcA; hi = g_Winh; lo = g_Winl; i = blk * blockDim.x + threadIdx.x; }
        else { src = srcB; hi = g_Wh1h; lo = g_Wh1l; i = (blk - half1) * blockDim.x + threadIdx.x; }
    } else {
        src = srcA; hi = g_Wh2h; lo = g_Wh2l; i = blk * blockDim.x + threadIdx.x;
    }
    if (i >= n4each) return;
    float4 v = reinterpret_cast<const float4*>(src)[i];
    __half h0 = __float2half_rn(v.x), h1 = __float2half_rn(v.y);
    __half h2 = __float2half_rn(v.z), h3 = __float2half_rn(v.w);
    __half2 a, b;
    a.x = h0; a.y = h1; b.x = h2; b.y = h3;
    reinterpret_cast<__half2*>(hi)[2 * i]     = a;
    reinterpret_cast<__half2*>(hi)[2 * i + 1] = b;
    a.x = __float2half_rn(v.x - __half2float(h0));
    a.y = __float2half_rn(v.y - __half2float(h1));
    b.x = __float2half_rn(v.z - __half2float(h2));
    b.y = __float2half_rn(v.w - __half2float(h3));
    reinterpret_cast<__half2*>(lo)[2 * i]     = a;
    reinterpret_cast<__half2*>(lo)[2 * i + 1] = b;
}

// -------------------- mma.sync fp16 2-product GEMM + bias + relu ------------
template <int BN, int SEL>
__global__ void __launch_bounds__(256, 2)
mma_gemm(const float* __restrict__ bias, int M, int N, int K)
{
    const __half* Ah = (SEL == 0) ? g_geomh : (SEL == 1) ? g_h0h : g_h1h;
    const __half* Bh = (SEL == 0) ? g_Winh  : (SEL == 1) ? g_Wh1h : g_Wh2h;
    const __half* Bl = (SEL == 0) ? g_Winl  : (SEL == 1) ? g_Wh1l : g_Wh2l;

    constexpr int ASTG = 8192;
    constexpr int BSTG = BN * 64;
    constexpr int WN   = BN / 4;
    constexpr int NFR  = WN / 16;
    constexpr int NNI  = WN / 8;

    extern __shared__ __align__(16) char dsm[];
    const uint32_t sb  = smem_u32(dsm);
    const uint32_t bA  = sb;
    const uint32_t bBh = sb + 3 * ASTG;
    const uint32_t bBl = bBh + 3 * BSTG;

    const int tid = threadIdx.x;
    const int warp = tid >> 5, lane = tid & 31;
    const int wm = warp >> 2, wn = warp & 3;
    const int m0 = blockIdx.y * 128, n0 = blockIdx.x * BN;

    float acc[4][NNI][4];
#pragma unroll
    for (int i = 0; i < 4; i++)
#pragma unroll
        for (int j = 0; j < NNI; j++)
#pragma unroll
            for (int q = 0; q < 4; q++) acc[i][j][q] = 0.f;

    const int row_off = (lane & 7) | (((lane >> 3) & 1) << 3);
    const int cc_half = lane >> 4;
    const int ldr = tid >> 2, ldc = tid & 3;
    const uint32_t oA0 = SWOFF(ldr, ldc), oA1 = SWOFF(ldr + 64, ldc);
    const int nchunk = K >> 5;

#define LOAD_STAGE(kc, bf) do {                                                 \
        int _k0 = (kc) << 5;                                                    \
        uint32_t _oa = (uint32_t)(bf) * ASTG, _ob = (uint32_t)(bf) * BSTG;      \
        size_t _g0 = (size_t)(m0 + ldr) * K + _k0 + ldc * 8;                    \
        size_t _g1 = (size_t)(m0 + ldr + 64) * K + _k0 + ldc * 8;               \
        cp16(bA + _oa + oA0, Ah + _g0);                                         \
        cp16(bA + _oa + oA1, Ah + _g1);                                         \
        size_t _gb0 = (size_t)(n0 + ldr) * K + _k0 + ldc * 8;                   \
        cp16(bBh + _ob + oA0, Bh + _gb0);                                       \
        cp16(bBl + _ob + oA0, Bl + _gb0);                                       \
        if (BN == 128) {                                                        \
            size_t _gb1 = (size_t)(n0 + ldr + 64) * K + _k0 + ldc * 8;          \
            cp16(bBh + _ob + oA1, Bh + _gb1);                                   \
            cp16(bBl + _ob + oA1, Bl + _gb1);                                   \
        }                                                                       \
    } while (0)

    LOAD_STAGE(0, 0); CP_COMMIT();
    LOAD_STAGE(1, 1); CP_COMMIT();

    for (int kc = 0; kc < nchunk; kc++) {
        if (kc + 1 < nchunk) { CP_WAIT(1); } else { CP_WAIT(0); }
        __syncthreads();
        if (kc + 2 < nchunk) {
            LOAD_STAGE(kc + 2, (kc + 2) % 3);
            CP_COMMIT();
        }
        const int bf = kc % 3;
        const uint32_t oa = (uint32_t)bf * ASTG, ob = (uint32_t)bf * BSTG;
#pragma unroll
        for (int s = 0; s < 2; s++) {
            const int cc = 2 * s + cc_half;
            uint32_t Af[4][4], Bfh[4 * NFR], Bfl[4 * NFR];
#pragma unroll
            for (int mi = 0; mi < 4; mi++) {
                int r = wm * 64 + mi * 16 + row_off;
                ldsm_x4(Af[mi], bA + oa + SWOFF(r, cc));
            }
#pragma unroll
            for (int f = 0; f < NFR; f++) {
                int r = wn * WN + f * 16 + row_off;
                ldsm_x4(Bfh + 4 * f, bBh + ob + SWOFF(r, cc));
                ldsm_x4(Bfl + 4 * f, bBl + ob + SWOFF(r, cc));
            }
#pragma unroll
            for (int mi = 0; mi < 4; mi++) {
#pragma unroll
                for (int ni = 0; ni < NNI; ni++) {
                    const int q = (ni >> 1) * 4 + (ni & 1);
                    mma16816(acc[mi][ni], Af[mi], Bfh[q], Bfh[q + 2]);
                    mma16816(acc[mi][ni], Af[mi], Bfl[q], Bfl[q + 2]);
                }
            }
        }
    }
#undef LOAD_STAGE

    const int g = lane >> 2, tg = lane & 3;
#pragma unroll
    for (int mi = 0; mi < 4; mi++) {
#pragma unroll
        for (int ni = 0; ni < NNI; ni++) {
            int col = n0 + wn * WN + ni * 8 + 2 * tg;
            float b0 = bias[col], b1 = bias[col + 1];
#pragma unroll
            for (int h = 0; h < 2; h++) {
                int row = m0 + wm * 64 + mi * 16 + g + h * 8;
                float v0 = acc[mi][ni][2 * h + 0] + b0;
                float v1 = acc[mi][ni][2 * h + 1] + b1;
                v0 = v0 > 0.f ? v0 : 0.f;
                v1 = v1 > 0.f ? v1 : 0.f;
                size_t idx = (size_t)row * N + col;
                if (SEL == 2) {
                    *reinterpret_cast<float2*>(g_xr + idx) = make_float2(v0, v1);
                } else {
                    __half* Ch = (SEL == 0) ? g_h0h : g_h1h;
                    __half2 hh;
                    hh.x = __float2half_rn(v0);
                    hh.y = __float2half_rn(v1);
                    *reinterpret_cast<__half2*>(Ch + idx) = hh;
                }
            }
        }
    }
}

// -------------------- table init (grid-stride, double precision) ------------
__global__ void init_tables(const float* __restrict__ w0,
                            const float* __restrict__ w1)
{
    const double TWO_PI = 6.283185307179586476925286766559;
    int gtid = blockIdx.x * blockDim.x + threadIdx.x;
    int nthr = gridDim.x * blockDim.x;
    for (int i = gtid; i < 32768; i += nthr) {
        double s, c;
        sincos(-TWO_PI * (double)i / 32768.0, &s, &c);
        g_btw[i] = make_float2((float)c, (float)s);
    }
    for (int i = gtid; i < 85; i += nthr) {
        int Ns, off;
        if (i < 1)       { Ns = 1;  off = 0; }
        else if (i < 5)  { Ns = 4;  off = 1; }
        else if (i < 21) { Ns = 16; off = 5; }
        else             { Ns = 64; off = 21; }
        int jm = i - off;
        for (int m = 1; m <= 3; m++) {
            double s, c;
            sincos(-TWO_PI * (double)(m * jm) / (double)(4 * Ns), &s, &c);
            g_r4a[i * 3 + m - 1] = make_float2((float)c, (float)s);
        }
    }
    for (int i = gtid; i < 42; i += nthr) {
        int Ns, off;
        if (i < 2)       { Ns = 2;  off = 0; }
        else if (i < 10) { Ns = 8;  off = 2; }
        else             { Ns = 32; off = 10; }
        int jm = i - off;
        for (int m = 1; m <= 3; m++) {
            double s, c;
            sincos(-TWO_PI * (double)(m * jm) / (double)(4 * Ns), &s, &c);
            g_r4b[i * 3 + m - 1] = make_float2((float)c, (float)s);
        }
    }
    for (int i = gtid; i < 4096; i += nthr) {
        int a = i >> 6, b = i & 63;
        int t = (a * b) & 63;
        double s, c;
        sincos(-TWO_PI * (double)t / 64.0, &s, &c);
        float cf = (float)c, sf = (float)s;
        g_dftF[i]  = make_float2(cf, sf);
        g_dftFn[i] = make_float2(-sf, cf);
        float ci = (float)(c / 64.0), si = (float)(-s / 64.0);
        g_dftI[i]  = make_float2(ci, si);
        g_dftIn[i] = make_float2(-si, ci);
    }
    for (int w = gtid; w < 64; w += nthr) {
        double pr = 0, pi = 0, mr = 0, mi = 0;
        for (int m = 0; m < 32; m++) {
            float a = w0[m * 64 + w];
            float b = w1[m * 64 + w];
            double s, c;
            sincos(TWO_PI * (double)m / 32.0, &s, &c);
            double coef = (double)b * fabs((double)a);
            if (a >= 0.0f) { pr += coef * c; pi += coef * s; }
            else           { mr += coef * c; mi += coef * s; }
        }
        g_P[w] = make_float2((float)pr, (float)pi);
        g_M[w] = make_float2((float)mr, (float)mi);
    }
}

// -------------------- batch-axis FFT, step 1: 256-pt radix-4 ----------------
template <int REAL>
__global__ __launch_bounds__(256)
void fft_b_step1(float fs)
{
    __shared__ float2 s0[8][256];
    __shared__ float2 s1[8][256];
    __shared__ float2 stw[255];
    int tid = threadIdx.x;
    int n1 = blockIdx.x;
    int c0 = blockIdx.y << 3;
    for (int i = tid; i < 255; i += 256) stw[i] = g_r4a[i];
    for (int i = tid; i < 2048; i += 256) {
        int n2 = i >> 3, ch = i & 7;
        size_t gi = (size_t)(n1 + (n2 << 7)) * 64 + c0 + ch;
        if (REAL) s0[ch][n2] = make_float2(g_xr[gi], 0.f);
        else      s0[ch][n2] = g_bufA[gi];
    }
    __syncthreads();
    float2 (*src)[256] = s0;
    float2 (*dst)[256] = s1;
#pragma unroll
    for (int st = 0; st < 4; st++) {
        const int Ns = 1 << (2 * st);
        const int off = (Ns - 1) / 3;
        for (int u = tid; u < 512; u += 256) {
            int ch = u >> 6, j = u & 63;
            int jm = j & (Ns - 1);
            int tb = (off + jm) * 3;
            float2 w1 = stw[tb], w2 = stw[tb + 1], w3 = stw[tb + 2];
            float w1y = fs * w1.y, w2y = fs * w2.y, w3y = fs * w3.y;
            u64t a = *(const u64t*)&src[ch][j];
            float2 b = src[ch][j + 64];
            float2 c = src[ch][j + 128];
            float2 d = src[ch][j + 192];
            u64t bw = pk2(b.x * w1.x - b.y * w1y, b.x * w1y + b.y * w1.x);
            u64t cw = pk2(c.x * w2.x - c.y * w2y, c.x * w2y + c.y * w2.x);
            u64t dw = pk2(d.x * w3.x - d.y * w3y, d.x * w3y + d.y * w3.x);
            u64t t0 = add2(a, cw), t1 = sub2(a, cw);
            u64t t2 = add2(bw, dw), u3 = sub2(bw, dw);
            float2 u3f = u2f(u3);
            u64t t3 = pk2(fs * u3f.y, -fs * u3f.x);
            int idxD = ((j - jm) << 2) + jm;
            *(u64t*)&dst[ch][idxD]          = add2(t0, t2);
            *(u64t*)&dst[ch][idxD + Ns]     = add2(t1, t3);
            *(u64t*)&dst[ch][idxD + 2 * Ns] = sub2(t0, t2);
            *(u64t*)&dst[ch][idxD + 3 * Ns] = sub2(t1, t3);
        }
        __syncthreads();
        float2 (*tmp)[256] = src; src = dst; dst = tmp;
    }
    for (int i = tid; i < 2048; i += 256) {
        int k2 = i >> 3, ch = i & 7;
        float2 w = g_btw[(n1 * k2) & 32767];
        float c = w.x, s = fs * w.y;
        float2 v = src[ch][k2];
        g_Z[((size_t)k2 * 128 + n1) * 64 + c0 + ch] =
            make_float2(v.x * c - v.y * s, v.x * s + v.y * c);
    }
}

// -------------------- batch-axis FFT, step 2: 128-pt (radix-2 + 3x radix-4) -
__global__ __launch_bounds__(256)
void fft_b_step2(float fs, float scale)
{
    __shared__ float2 s0[8][128];
    __shared__ float2 s1[8][128];
    __shared__ float2 stw[126];
    int tid = threadIdx.x;
    int k2 = blockIdx.x;
    int c0 = blockIdx.y << 3;
    for (int i = tid; i < 126; i += 256) stw[i] = g_r4b[i];
    for (int i = tid; i < 1024; i += 256) {
        int n1 = i >> 3, ch = i & 7;
        s0[ch][n1] = g_Z[((size_t)k2 * 128 + n1) * 64 + c0 + ch];
    }
    __syncthreads();
    for (int u = tid; u < 512; u += 256) {
        int ch = u >> 6, j = u & 63;
        u64t a = *(const u64t*)&s0[ch][j];
        u64t b = *(const u64t*)&s0[ch][j + 64];
        *(u64t*)&s1[ch][2 * j]     = add2(a, b);
        *(u64t*)&s1[ch][2 * j + 1] = sub2(a, b);
    }
    __syncthreads();
    float2 (*src)[128] = s1;
    float2 (*dst)[128] = s0;
#pragma unroll
    for (int st = 0; st < 3; st++) {
        const int Ns = 2 << (2 * st);
        const int off = (Ns - 2) / 3;
        {
            int ch = tid >> 5, j = tid & 31;
            int jm = j & (Ns - 1);
            int tb = (off + jm) * 3;
            float2 w1 = stw[tb], w2 = stw[tb + 1], w3 = stw[tb + 2];
            float w1y = fs * w1.y, w2y = fs * w2.y, w3y = fs * w3.y;
            u64t a = *(const u64t*)&src[ch][j];
            float2 b = src[ch][j + 32];
            float2 c = src[ch][j + 64];
            float2 d = src[ch][j + 96];
            u64t bw = pk2(b.x * w1.x - b.y * w1y, b.x * w1y + b.y * w1.x);
            u64t cw = pk2(c.x * w2.x - c.y * w2y, c.x * w2y + c.y * w2.x);
            u64t dw = pk2(d.x * w3.x - d.y * w3y, d.x * w3y + d.y * w3.x);
            u64t t0 = add2(a, cw), t1 = sub2(a, cw);
            u64t t2 = add2(bw, dw), u3 = sub2(bw, dw);
            float2 u3f = u2f(u3);
            u64t t3 = pk2(fs * u3f.y, -fs * u3f.x);
            int idxD = ((j - jm) << 2) + jm;
            *(u64t*)&dst[ch][idxD]          = add2(t0, t2);
            *(u64t*)&dst[ch][idxD + Ns]     = add2(t1, t3);
            *(u64t*)&dst[ch][idxD + 2 * Ns] = sub2(t0, t2);
            *(u64t*)&dst[ch][idxD + 3 * Ns] = sub2(t1, t3);
        }
        __syncthreads();
        float2 (*tmp)[128] = src; src = dst; dst = tmp;
    }
    for (int i = tid; i < 1024; i += 256) {
        int k1 = i >> 3, ch = i & 7;
        float2 v = src[ch][k1];
        g_bufB[(size_t)(k2 + (k1 << 8)) * 64 + c0 + ch] =
            make_float2(v.x * scale, v.y * scale);
    }
}

// -------------------- FNO core: row DFT + P/M + lin1 + lin2 (packed) --------
__global__ __launch_bounds__(256)
void mid_kernel(const float* __restrict__ lin1W, const float* __restrict__ lin1b,
                const float* __restrict__ lin2W, const float* __restrict__ lin2b)
{
    __shared__ float L1t[64 * 65];
    __shared__ float L2t[64 * 65];
    __shared__ float2 zc[16][64];
    __shared__ float2 yc[16][64];
    __shared__ float2 sP[64], sM[64];
    int tid = threadIdx.x;
    int row0 = blockIdx.x << 4;
    for (int i = tid; i < 4096; i += 256) {
        int o = i >> 6, w = i & 63;
        L1t[o * 65 + w] = lin1W[i];
        L2t[o * 65 + w] = lin2W[i];
    }
    if (tid < 64) { sP[tid] = g_P[tid]; sM[tid] = g_M[tid]; }
    for (int i = tid; i < 1024; i += 256) {
        int r = i >> 6, w = i & 63;
        zc[r][w] = g_bufB[(size_t)(row0 + r) * 64 + w];
    }
    __syncthreads();
    const int r0 = (tid >> 5) << 1, r1 = r0 + 1;
    const int w0 = tid & 31, w1 = w0 + 32;
    // ---- row DFT-64, 2x2 outputs (packed complex MAC) ----
    u64t a00 = 0, a01 = 0, a10 = 0, a11 = 0;
#pragma unroll 8
    for (int ww = 0; ww < 64; ww++) {
        float2 z0 = zc[r0][ww], z1 = zc[r1][ww];
        u64t z0x = pk2(z0.x, z0.x), z0y = pk2(z0.y, z0.y);
        u64t z1x = pk2(z1.x, z1.x), z1y = pk2(z1.y, z1.y);
        u64t t0p = *(const u64t*)&g_dftF[(ww << 6) + w0];
        u64t t0n = *(const u64t*)&g_dftFn[(ww << 6) + w0];
        u64t t1p = *(const u64t*)&g_dftF[(ww << 6) + w1];
        u64t t1n = *(const u64t*)&g_dftFn[(ww << 6) + w1];
        a00 = fma2(z0x, t0p, a00); a00 = fma2(z0y, t0n, a00);
        a01 = fma2(z0x, t1p, a01); a01 = fma2(z0y, t1n, a01);
        a10 = fma2(z1x, t0p, a10); a10 = fma2(z1y, t0n, a10);
        a11 = fma2(z1x, t1p, a11); a11 = fma2(z1y, t1n, a11);
    }
    // ---- P/M crelu collapse ----
    {
        float2 P0 = sP[w0], M0 = sM[w0], P1 = sP[w1], M1 = sM[w1];
#define PM(av, P, Mv, dstp)                                                 \
        {                                                                   \
            float2 x = u2f(av);                                             \
            float rp = fmaxf(x.x, 0.f), rn = fmaxf(-x.x, 0.f);              \
            float ip = fmaxf(x.y, 0.f), iq = fmaxf(-x.y, 0.f);              \
            dstp = make_float2(rp * P.x - ip * P.y + rn * Mv.x - iq * Mv.y, \
                               rp * P.y + ip * P.x + rn * Mv.y + iq * Mv.x);\
        }
        PM(a00, P0, M0, yc[r0][w0])
        PM(a01, P1, M1, yc[r0][w1])
        PM(a10, P0, M0, yc[r1][w0])
        PM(a11, P1, M1, yc[r1][w1])
#undef PM
    }
    __syncthreads();
    // ---- lin1 (+bias, crelu), packed ----
    u64t s00 = pk2(lin1b[w0], 0.f), s01 = pk2(lin1b[w1], 0.f);
    u64t s10 = s00, s11 = s01;
#pragma unroll 8
    for (int ww = 0; ww < 64; ww++) {
        u64t y0 = *(const u64t*)&yc[r0][ww];
        u64t y1 = *(const u64t*)&yc[r1][ww];
        float u0 = L1t[w0 * 65 + ww], u1 = L1t[w1 * 65 + ww];
        u64t u0p = pk2(u0, u0), u1p = pk2(u1, u1);
        s00 = fma2(u0p, y0, s00); s01 = fma2(u1p, y0, s01);
        s10 = fma2(u0p, y1, s10); s11 = fma2(u1p, y1, s11);
    }
    float2 f00 = u2f(s00), f01 = u2f(s01), f10 = u2f(s10), f11 = u2f(s11);
    f00.x = fmaxf(f00.x, 0.f); f00.y = fmaxf(f00.y, 0.f);
    f01.x = fmaxf(f01.x, 0.f); f01.y = fmaxf(f01.y, 0.f);
    f10.x = fmaxf(f10.x, 0.f); f10.y = fmaxf(f10.y, 0.f);
    f11.x = fmaxf(f11.x, 0.f); f11.y = fmaxf(f11.y, 0.f);
    __syncthreads();
    yc[r0][w0] = f00; yc[r0][w1] = f01;
    yc[r1][w0] = f10; yc[r1][w1] = f11;
    __syncthreads();
    // ---- lin2 (+bias), packed -> g_bufA ----
    s00 = pk2(lin2b[w0], 0.f); s01 = pk2(lin2b[w1], 0.f);
    s10 = s00; s11 = s01;
#pragma unroll 8
    for (int ww = 0; ww < 64; ww++) {
        u64t y0 = *(const u64t*)&yc[r0][ww];
        u64t y1 = *(const u64t*)&yc[r1][ww];
        float u0 = L2t[w0 * 65 + ww], u1 = L2t[w1 * 65 + ww];
        u64t u0p = pk2(u0, u0), u1p = pk2(u1, u1);
        s00 = fma2(u0p, y0, s00); s01 = fma2(u1p, y0, s01);
        s10 = fma2(u0p, y1, s10); s11 = fma2(u1p, y1, s11);
    }
    g_bufA[(size_t)(row0 + r0) * 64 + w0] = u2f(s00);
    g_bufA[(size_t)(row0 + r0) * 64 + w1] = u2f(s01);
    g_bufA[(size_t)(row0 + r1) * 64 + w0] = u2f(s10);
    g_bufA[(size_t)(row0 + r1) * 64 + w1] = u2f(s11);
}

// -------------------- inverse row DFT-64 + W_out (packed) -------------------
__global__ __launch_bounds__(256)
void out_kernel(const float* __restrict__ Wout, const float* __restrict__ bout,
                float* __restrict__ outp, int interleaved)
{
    __shared__ float Wt[128 * 65];
    __shared__ float2 zc[16][64];
    __shared__ float2 su[16][64];
    int tid = threadIdx.x;
    int row0 = blockIdx.x << 4;
    for (int i = tid; i < 8192; i += 256) {
        int f = i >> 6, w = i & 63;
        Wt[f * 65 + w] = Wout[i];
    }
    for (int i = tid; i < 1024; i += 256) {
        int r = i >> 6, w = i & 63;
        zc[r][w] = g_bufB[(size_t)(row0 + r) * 64 + w];
    }
    __syncthreads();
    const int r0 = (tid >> 5) << 1, r1 = r0 + 1;
    const int w0 = tid & 31, w1 = w0 + 32;
    // ---- inverse row DFT-64, 2x2 outputs (packed) ----
    u64t a00 = 0, a01 = 0, a10 = 0, a11 = 0;
#pragma unroll 8
    for (int k = 0; k < 64; k++) {
        float2 z0 = zc[r0][k], z1 = zc[r1][k];
        u64t z0x = pk2(z0.x, z0.x), z0y = pk2(z0.y, z0.y);
        u64t z1x = pk2(z1.x, z1.x), z1y = pk2(z1.y, z1.y);
        u64t t0p = *(const u64t*)&g_dftI[(k << 6) + w0];
        u64t t0n = *(const u64t*)&g_dftIn[(k << 6) + w0];
        u64t t1p = *(const u64t*)&g_dftI[(k << 6) + w1];
        u64t t1n = *(const u64t*)&g_dftIn[(k << 6) + w1];
        a00 = fma2(z0x, t0p, a00); a00 = fma2(z0y, t0n, a00);
        a01 = fma2(z0x, t1p, a01); a01 = fma2(z0y, t1n, a01);
        a10 = fma2(z1x, t0p, a10); a10 = fma2(z1y, t0n, a10);
        a11 = fma2(z1x, t1p, a11); a11 = fma2(z1y, t1n, a11);
    }
    *(u64t*)&su[r0][w0] = a00;
    *(u64t*)&su[r0][w1] = a01;
    *(u64t*)&su[r1][w0] = a10;
    *(u64t*)&su[r1][w1] = a11;
    __syncthreads();
    // ---- W_out projection: 2 rows x 4 f-outputs per thread (packed) ----
    const int f0 = tid & 31;
    u64t p[2][4];
#pragma unroll
    for (int b = 0; b < 4; b++) {
        u64t bp = pk2(bout[f0 + 32 * b], 0.f);
        p[0][b] = bp; p[1][b] = bp;
    }
#pragma unroll 8
    for (int w = 0; w < 64; w++) {
        u64t u0 = *(const u64t*)&su[r0][w];
        u64t u1 = *(const u64t*)&su[r1][w];
        float w0v = Wt[(f0)      * 65 + w];
        float w1v = Wt[(f0 + 32) * 65 + w];
        float w2v = Wt[(f0 + 64) * 65 + w];
        float w3v = Wt[(f0 + 96) * 65 + w];
        u64t w0p = pk2(w0v, w0v), w1p = pk2(w1v, w1v);
        u64t w2p = pk2(w2v, w2v), w3p = pk2(w3v, w3v);
        p[0][0] = fma2(w0p, u0, p[0][0]); p[0][1] = fma2(w1p, u0, p[0][1]);
        p[0][2] = fma2(w2p, u0, p[0][2]); p[0][3] = fma2(w3p, u0, p[0][3]);
        p[1][0] = fma2(w0p, u1, p[1][0]); p[1][1] = fma2(w1p, u1, p[1][1]);
        p[1][2] = fma2(w2p, u1, p[1][2]); p[1][3] = fma2(w3p, u1, p[1][3]);
    }
#pragma unroll
    for (int a = 0; a < 2; a++) {
        int row = row0 + (a == 0 ? r0 : r1);
#pragma unroll
        for (int b = 0; b < 4; b++) {
            float2 v = u2f(p[a][b]);
            size_t oidx = (size_t)row * 128 + f0 + 32 * b;
            if (interleaved) {
                reinterpret_cast<float2*>(outp)[oidx] = v;
            } else {
                outp[oidx] = v.x;
            }
        }
    }
}

// ---------------------------------------------------------------------------
extern "C" void kernel_launch(void* const* d_in, const int* in_sizes, int n_in,
                              void* d_out, int out_size)
{
    (void)in_sizes; (void)n_in;
    const float* geom  = (const float*)d_in[0];
    const float* W_in  = (const float*)d_in[1];
    const float* b_in  = (const float*)d_in[2];
    const float* W_h1  = (const float*)d_in[3];
    const float* b_h1  = (const float*)d_in[4];
    const float* W_h2  = (const float*)d_in[5];
    const float* b_h2  = (const float*)d_in[6];
    const float* w0    = (const float*)d_in[7];
    const float* w1    = (const float*)d_in[8];
    const float* lin1W = (const float*)d_in[9];
    const float* lin1b = (const float*)d_in[10];
    const float* lin2W = (const float*)d_in[11];
    const float* lin2b = (const float*)d_in[12];
    const float* Wout  = (const float*)d_in[13];
    const float* bout  = (const float*)d_in[14];

    const int GSM128 = 3 * 8192 + 6 * 128 * 64;   // 73728 bytes
    const int GSM64  = 3 * 8192 + 6 * 64 * 64;    // 49152 bytes
    cudaFuncSetAttribute(mma_gemm<128, 0>, cudaFuncAttributeMaxDynamicSharedMemorySize, GSM128);
    cudaFuncSetAttribute(mma_gemm<128, 1>, cudaFuncAttributeMaxDynamicSharedMemorySize, GSM128);
    cudaFuncSetAttribute(mma_gemm<64, 2>,  cudaFuncAttributeMaxDynamicSharedMemorySize, GSM64);

    // mma_gemm<128,1> (GEMM2) stays in the 4th-launch ncu capture slot
    split_geom<<<(NB * 512 / 4) / 256, 256>>>(geom, NB * 512 / 4);
    split_w<0><<<2 * (1024 * 512 / 4) / 256, 256>>>(W_in, W_h1, 1024 * 512 / 4);
    mma_gemm<128, 0><<<dim3(1024 / 128, NB / 128), 256, GSM128>>>(b_in, NB, 1024, 512);
    mma_gemm<128, 1><<<dim3(512 / 128, NB / 128), 256, GSM128>>>(b_h1, NB, 512, 1024);
    init_tables<<<64, 256>>>(w0, w1);
    split_w<1><<<(64 * 512 / 4) / 256, 256>>>(W_h2, nullptr, 64 * 512 / 4);
    mma_gemm<64, 2><<<dim3(1, NB / 128), 256, GSM64>>>(b_h2, NB, 64, 512);

    // forward batch FFT directly on real g_xr
    fft_b_step1<1><<<dim3(128, 8), 256>>>(1.f);
    fft_b_step2<<<dim3(256, 8), 256>>>(1.f, 1.0f);

    // FNO core: row DFT + P/M + lin1 + lin2
    mid_kernel<<<NB / 16, 256>>>(lin1W, lin1b, lin2W, lin2b);

    // inverse batch FFT (conjugated twiddles)
    fft_b_step1<0><<<dim3(128, 8), 256>>>(-1.f);
    fft_b_step2<<<dim3(256, 8), 256>>>(-1.f, 1.0f / 32768.0f);

    // inverse row DFT-64 + output projection
    int interleaved = (out_size >= 2 * NB * 128) ? 1 : 0;
    out_kernel<<<NB / 16, 256>>>(Wout, bout, (float*)d_out, interleaved);
}

// round 17
// speedup vs baseline: 1.3184x; 1.3184x over previous
#include <cuda_runtime.h>
#include <cuda_fp16.h>
#include <math.h>
#include <cstdint>

// ---------------------------------------------------------------------------
// FieldPredictionNetwork:  B=32768, G=512, H0=1024, H1=512, W=64, MODES=32, FD=128
// MLP GEMMs: plain fp16 mma.sync (single product; error budget verified),
//            CTA 128x128, BK=32, 3-stage cp.async, one barrier per chunk.
// FFT: batch-axis radix-4 Stockham; row DFT-64 fused into mid/out kernels.
// mid/out: register-tiled (2x2 / 2x4).
// ---------------------------------------------------------------------------

#define NB 32768

// -------------------- scratch (device globals) ------------------------------
__device__ __half g_geomh[NB * 512];
__device__ __half g_Winh[1024 * 512];
__device__ __half g_Wh1h[512 * 1024];
__device__ __half g_Wh2h[64 * 512];
__device__ __half g_h0h[NB * 1024];
__device__ __half g_h1h[NB * 512];
__device__ float  g_xr[NB * 64];
__device__ float2 g_bufA[NB * 64];
__device__ float2 g_bufB[NB * 64];
__device__ float2 g_Z[NB * 64];
__device__ float2 g_dftF[64 * 64];
__device__ float2 g_dftI[64 * 64];
__device__ float2 g_P[64];
__device__ float2 g_M[64];
__device__ float2 g_r4a[85 * 3];
__device__ float2 g_r4b[42 * 3];
__device__ float2 g_btw[32768];

// -------------------- small PTX wrappers ------------------------------------
__device__ __forceinline__ uint32_t smem_u32(const void* p) {
    uint32_t a;
    asm("{ .reg .u64 t; cvta.to.shared.u64 t, %1; cvt.u32.u64 %0, t; }" : "=r"(a) : "l"(p));
    return a;
}
__device__ __forceinline__ void ldsm_x4(uint32_t* r, uint32_t a) {
    asm volatile("ldmatrix.sync.aligned.m8n8.x4.shared.b16 {%0,%1,%2,%3}, [%4];"
                 : "=r"(r[0]), "=r"(r[1]), "=r"(r[2]), "=r"(r[3]) : "r"(a));
}
__device__ __forceinline__ void mma16816(float* c, const uint32_t* a,
                                         uint32_t b0, uint32_t b1) {
    asm volatile("mma.sync.aligned.m16n8k16.row.col.f32.f16.f16.f32 "
                 "{%0,%1,%2,%3}, {%4,%5,%6,%7}, {%8,%9}, {%0,%1,%2,%3};"
                 : "+f"(c[0]), "+f"(c[1]), "+f"(c[2]), "+f"(c[3])
                 : "r"(a[0]), "r"(a[1]), "r"(a[2]), "r"(a[3]), "r"(b0), "r"(b1));
}
__device__ __forceinline__ void cp16(uint32_t dst, const void* src) {
    asm volatile("cp.async.cg.shared.global [%0], [%1], 16;" :: "r"(dst), "l"(src));
}
#define CP_COMMIT()  asm volatile("cp.async.commit_group;" ::: "memory")
#define CP_WAIT(n)   asm volatile("cp.async.wait_group %0;" :: "n"(n) : "memory")

#define SWOFF(r, cc) ((uint32_t)((r) * 64 + (((cc) ^ (((r) >> 1) & 3)) << 4)))

// -------------------- fp32 -> fp16 conversions ------------------------------
__global__ void split_geom(const float* __restrict__ src, int n4)
{
    int i = blockIdx.x * blockDim.x + threadIdx.x;
    if (i >= n4) return;
    float4 v = reinterpret_cast<const float4*>(src)[i];
    __half2 a, b;
    a.x = __float2half_rn(v.x); a.y = __float2half_rn(v.y);
    b.x = __float2half_rn(v.z); b.y = __float2half_rn(v.w);
    reinterpret_cast<__half2*>(g_geomh)[2 * i]     = a;
    reinterpret_cast<__half2*>(g_geomh)[2 * i + 1] = b;
}

// SEL 0: W_in+W_h1 combined; SEL 1: W_h2.  Single-level fp16.
template <int SEL>
__global__ void split_w(const float* __restrict__ srcA,
                        const float* __restrict__ srcB, int n4each)
{
    int blk = blockIdx.x;
    const float* src;
    __half* hi;
    int i;
    if (SEL == 0) {
        int half1 = gridDim.x / 2;
        if (blk < half1) { src = srcA; hi = g_Winh; i = blk * blockDim.x + threadIdx.x; }
        else { src = srcB; hi = g_Wh1h; i = (blk - half1) * blockDim.x + threadIdx.x; }
    } else {
        src = srcA; hi = g_Wh2h; i = blk * blockDim.x + threadIdx.x;
    }
    if (i >= n4each) return;
    float4 v = reinterpret_cast<const float4*>(src)[i];
    __half2 a, b;
    a.x = __float2half_rn(v.x); a.y = __float2half_rn(v.y);
    b.x = __float2half_rn(v.z); b.y = __float2half_rn(v.w);
    reinterpret_cast<__half2*>(hi)[2 * i]     = a;
    reinterpret_cast<__half2*>(hi)[2 * i + 1] = b;
}

// -------------------- plain fp16 mma.sync GEMM + bias + relu ----------------
template <int BN, int SEL>
__global__ void __launch_bounds__(256, 2)
mma_gemm(const float* __restrict__ bias, int M, int N, int K)
{
    const __half* Ah = (SEL == 0) ? g_geomh : (SEL == 1) ? g_h0h : g_h1h;
    const __half* Bh = (SEL == 0) ? g_Winh  : (SEL == 1) ? g_Wh1h : g_Wh2h;

    constexpr int ASTG = 8192;          // 128 rows x 32 fp16
    constexpr int BSTG = BN * 64;
    constexpr int WN   = BN / 4;
    constexpr int NFR  = WN / 16;       // 1 (BN=64) or 2 (BN=128)
    constexpr int NNI  = WN / 8;        // 2 or 4

    extern __shared__ __align__(16) char dsm[];
    const uint32_t sb  = smem_u32(dsm);
    const uint32_t bA  = sb;                    // 3 x ASTG
    const uint32_t bBh = sb + 3 * ASTG;         // 3 x BSTG

    const int tid = threadIdx.x;
    const int warp = tid >> 5, lane = tid & 31;
    const int wm = warp >> 2, wn = warp & 3;
    const int m0 = blockIdx.y * 128, n0 = blockIdx.x * BN;

    float acc[4][NNI][4];
#pragma unroll
    for (int i = 0; i < 4; i++)
#pragma unroll
        for (int j = 0; j < NNI; j++)
#pragma unroll
            for (int q = 0; q < 4; q++) acc[i][j][q] = 0.f;

    const int row_off = (lane & 7) | (((lane >> 3) & 1) << 3);
    const int cc_half = lane >> 4;
    const int ldr = tid >> 2, ldc = tid & 3;
    const uint32_t oA0 = SWOFF(ldr, ldc), oA1 = SWOFF(ldr + 64, ldc);
    const int nchunk = K >> 5;

#define LOAD_STAGE(kc, bf) do {                                                 \
        int _k0 = (kc) << 5;                                                    \
        uint32_t _oa = (uint32_t)(bf) * ASTG, _ob = (uint32_t)(bf) * BSTG;      \
        size_t _g0 = (size_t)(m0 + ldr) * K + _k0 + ldc * 8;                    \
        size_t _g1 = (size_t)(m0 + ldr + 64) * K + _k0 + ldc * 8;               \
        cp16(bA + _oa + oA0, Ah + _g0);                                         \
        cp16(bA + _oa + oA1, Ah + _g1);                                         \
        size_t _gb0 = (size_t)(n0 + ldr) * K + _k0 + ldc * 8;                   \
        cp16(bBh + _ob + oA0, Bh + _gb0);                                       \
        if (BN == 128) {                                                        \
            size_t _gb1 = (size_t)(n0 + ldr + 64) * K + _k0 + ldc * 8;          \
            cp16(bBh + _ob + oA1, Bh + _gb1);                                   \
        }                                                                       \
    } while (0)

    LOAD_STAGE(0, 0); CP_COMMIT();
    LOAD_STAGE(1, 1); CP_COMMIT();

    for (int kc = 0; kc < nchunk; kc++) {
        if (kc + 1 < nchunk) { CP_WAIT(1); } else { CP_WAIT(0); }
        __syncthreads();
        if (kc + 2 < nchunk) {
            LOAD_STAGE(kc + 2, (kc + 2) % 3);
            CP_COMMIT();
        }
        const int bf = kc % 3;
        const uint32_t oa = (uint32_t)bf * ASTG, ob = (uint32_t)bf * BSTG;
#pragma unroll
        for (int s = 0; s < 2; s++) {
            const int cc = 2 * s + cc_half;
            uint32_t Af[4][4], Bf[4 * NFR];
#pragma unroll
            for (int mi = 0; mi < 4; mi++) {
                int r = wm * 64 + mi * 16 + row_off;
                ldsm_x4(Af[mi], bA + oa + SWOFF(r, cc));
            }
#pragma unroll
            for (int f = 0; f < NFR; f++) {
                int r = wn * WN + f * 16 + row_off;
                ldsm_x4(Bf + 4 * f, bBh + ob + SWOFF(r, cc));
            }
#pragma unroll
            for (int mi = 0; mi < 4; mi++) {
#pragma unroll
                for (int ni = 0; ni < NNI; ni++) {
                    const int q = (ni >> 1) * 4 + (ni & 1);
                    mma16816(acc[mi][ni], Af[mi], Bf[q], Bf[q + 2]);
                }
            }
        }
    }
#undef LOAD_STAGE

    const int g = lane >> 2, tg = lane & 3;
#pragma unroll
    for (int mi = 0; mi < 4; mi++) {
#pragma unroll
        for (int ni = 0; ni < NNI; ni++) {
            int col = n0 + wn * WN + ni * 8 + 2 * tg;
            float b0 = bias[col], b1 = bias[col + 1];
#pragma unroll
            for (int h = 0; h < 2; h++) {
                int row = m0 + wm * 64 + mi * 16 + g + h * 8;
                float v0 = acc[mi][ni][2 * h + 0] + b0;
                float v1 = acc[mi][ni][2 * h + 1] + b1;
                v0 = v0 > 0.f ? v0 : 0.f;
                v1 = v1 > 0.f ? v1 : 0.f;
                size_t idx = (size_t)row * N + col;
                if (SEL == 2) {
                    *reinterpret_cast<float2*>(g_xr + idx) = make_float2(v0, v1);
                } else {
                    __half* Ch = (SEL == 0) ? g_h0h : g_h1h;
                    __half2 hh;
                    hh.x = __float2half_rn(v0);
                    hh.y = __float2half_rn(v1);
                    *reinterpret_cast<__half2*>(Ch + idx) = hh;
                }
            }
        }
    }
}

// -------------------- table init (grid-stride, double precision) ------------
__global__ void init_tables(const float* __restrict__ w0,
                            const float* __restrict__ w1)
{
    const double TWO_PI = 6.283185307179586476925286766559;
    int gtid = blockIdx.x * blockDim.x + threadIdx.x;
    int nthr = gridDim.x * blockDim.x;
    for (int i = gtid; i < 32768; i += nthr) {
        double s, c;
        sincos(-TWO_PI * (double)i / 32768.0, &s, &c);
        g_btw[i] = make_float2((float)c, (float)s);
    }
    for (int i = gtid; i < 85; i += nthr) {
        int Ns, off;
        if (i < 1)       { Ns = 1;  off = 0; }
        else if (i < 5)  { Ns = 4;  off = 1; }
        else if (i < 21) { Ns = 16; off = 5; }
        else             { Ns = 64; off = 21; }
        int jm = i - off;
        for (int m = 1; m <= 3; m++) {
            double s, c;
            sincos(-TWO_PI * (double)(m * jm) / (double)(4 * Ns), &s, &c);
            g_r4a[i * 3 + m - 1] = make_float2((float)c, (float)s);
        }
    }
    for (int i = gtid; i < 42; i += nthr) {
        int Ns, off;
        if (i < 2)       { Ns = 2;  off = 0; }
        else if (i < 10) { Ns = 8;  off = 2; }
        else             { Ns = 32; off = 10; }
        int jm = i - off;
        for (int m = 1; m <= 3; m++) {
            double s, c;
            sincos(-TWO_PI * (double)(m * jm) / (double)(4 * Ns), &s, &c);
            g_r4b[i * 3 + m - 1] = make_float2((float)c, (float)s);
        }
    }
    for (int i = gtid; i < 4096; i += nthr) {
        int a = i >> 6, b = i & 63;
        int t = (a * b) & 63;
        double s, c;
        sincos(-TWO_PI * (double)t / 64.0, &s, &c);
        g_dftF[i] = make_float2((float)c, (float)s);
        g_dftI[i] = make_float2((float)(c / 64.0), (float)(-s / 64.0));
    }
    for (int w = gtid; w < 64; w += nthr) {
        double pr = 0, pi = 0, mr = 0, mi = 0;
        for (int m = 0; m < 32; m++) {
            float a = w0[m * 64 + w];
            float b = w1[m * 64 + w];
            double s, c;
            sincos(TWO_PI * (double)m / 32.0, &s, &c);
            double coef = (double)b * fabs((double)a);
            if (a >= 0.0f) { pr += coef * c; pi += coef * s; }
            else           { mr += coef * c; mi += coef * s; }
        }
        g_P[w] = make_float2((float)pr, (float)pi);
        g_M[w] = make_float2((float)mr, (float)mi);
    }
}

// -------------------- batch-axis FFT, step 1: 256-pt radix-4 ----------------
template <int REAL>
__global__ __launch_bounds__(256)
void fft_b_step1(float fs)
{
    __shared__ float2 s0[8][256];
    __shared__ float2 s1[8][256];
    __shared__ float2 stw[255];
    int tid = threadIdx.x;
    int n1 = blockIdx.x;
    int c0 = blockIdx.y << 3;
    for (int i = tid; i < 255; i += 256) stw[i] = g_r4a[i];
    for (int i = tid; i < 2048; i += 256) {
        int n2 = i >> 3, ch = i & 7;
        size_t gi = (size_t)(n1 + (n2 << 7)) * 64 + c0 + ch;
        if (REAL) s0[ch][n2] = make_float2(g_xr[gi], 0.f);
        else      s0[ch][n2] = g_bufA[gi];
    }
    __syncthreads();
    float2 (*src)[256] = s0;
    float2 (*dst)[256] = s1;
#pragma unroll
    for (int st = 0; st < 4; st++) {
        const int Ns = 1 << (2 * st);
        const int off = (Ns - 1) / 3;
        for (int u = tid; u < 512; u += 256) {
            int ch = u >> 6, j = u & 63;
            int jm = j & (Ns - 1);
            int tb = (off + jm) * 3;
            float2 w1 = stw[tb], w2 = stw[tb + 1], w3 = stw[tb + 2];
            float w1y = fs * w1.y, w2y = fs * w2.y, w3y = fs * w3.y;
            float2 a = src[ch][j];
            float2 b = src[ch][j + 64];
            float2 c = src[ch][j + 128];
            float2 d = src[ch][j + 192];
            float2 bw = make_float2(b.x * w1.x - b.y * w1y, b.x * w1y + b.y * w1.x);
            float2 cw = make_float2(c.x * w2.x - c.y * w2y, c.x * w2y + c.y * w2.x);
            float2 dw = make_float2(d.x * w3.x - d.y * w3y, d.x * w3y + d.y * w3.x);
            float2 t0 = make_float2(a.x + cw.x, a.y + cw.y);
            float2 t1 = make_float2(a.x - cw.x, a.y - cw.y);
            float2 t2 = make_float2(bw.x + dw.x, bw.y + dw.y);
            float2 u3 = make_float2(bw.x - dw.x, bw.y - dw.y);
            float2 t3 = make_float2(fs * u3.y, -fs * u3.x);
            int idxD = ((j - jm) << 2) + jm;
            dst[ch][idxD]          = make_float2(t0.x + t2.x, t0.y + t2.y);
            dst[ch][idxD + Ns]     = make_float2(t1.x + t3.x, t1.y + t3.y);
            dst[ch][idxD + 2 * Ns] = make_float2(t0.x - t2.x, t0.y - t2.y);
            dst[ch][idxD + 3 * Ns] = make_float2(t1.x - t3.x, t1.y - t3.y);
        }
        __syncthreads();
        float2 (*tmp)[256] = src; src = dst; dst = tmp;
    }
    for (int i = tid; i < 2048; i += 256) {
        int k2 = i >> 3, ch = i & 7;
        float2 w = g_btw[(n1 * k2) & 32767];
        float c = w.x, s = fs * w.y;
        float2 v = src[ch][k2];
        g_Z[((size_t)k2 * 128 + n1) * 64 + c0 + ch] =
            make_float2(v.x * c - v.y * s, v.x * s + v.y * c);
    }
}

// -------------------- batch-axis FFT, step 2: 128-pt (radix-2 + 3x radix-4) -
__global__ __launch_bounds__(256)
void fft_b_step2(float fs, float scale)
{
    __shared__ float2 s0[8][128];
    __shared__ float2 s1[8][128];
    __shared__ float2 stw[126];
    int tid = threadIdx.x;
    int k2 = blockIdx.x;
    int c0 = blockIdx.y << 3;
    for (int i = tid; i < 126; i += 256) stw[i] = g_r4b[i];
    for (int i = tid; i < 1024; i += 256) {
        int n1 = i >> 3, ch = i & 7;
        s0[ch][n1] = g_Z[((size_t)k2 * 128 + n1) * 64 + c0 + ch];
    }
    __syncthreads();
    for (int u = tid; u < 512; u += 256) {
        int ch = u >> 6, j = u & 63;
        float2 a = s0[ch][j], b = s0[ch][j + 64];
        s1[ch][2 * j]     = make_float2(a.x + b.x, a.y + b.y);
        s1[ch][2 * j + 1] = make_float2(a.x - b.x, a.y - b.y);
    }
    __syncthreads();
    float2 (*src)[128] = s1;
    float2 (*dst)[128] = s0;
#pragma unroll
    for (int st = 0; st < 3; st++) {
        const int Ns = 2 << (2 * st);
        const int off = (Ns - 2) / 3;
        {
            int ch = tid >> 5, j = tid & 31;
            int jm = j & (Ns - 1);
            int tb = (off + jm) * 3;
            float2 w1 = stw[tb], w2 = stw[tb + 1], w3 = stw[tb + 2];
            float w1y = fs * w1.y, w2y = fs * w2.y, w3y = fs * w3.y;
            float2 a = src[ch][j];
            float2 b = src[ch][j + 32];
            float2 c = src[ch][j + 64];
            float2 d = src[ch][j + 96];
            float2 bw = make_float2(b.x * w1.x - b.y * w1y, b.x * w1y + b.y * w1.x);
            float2 cw = make_float2(c.x * w2.x - c.y * w2y, c.x * w2y + c.y * w2.x);
            float2 dw = make_float2(d.x * w3.x - d.y * w3y, d.x * w3y + d.y * w3.x);
            float2 t0 = make_float2(a.x + cw.x, a.y + cw.y);
            float2 t1 = make_float2(a.x - cw.x, a.y - cw.y);
            float2 t2 = make_float2(bw.x + dw.x, bw.y + dw.y);
            float2 u3 = make_float2(bw.x - dw.x, bw.y - dw.y);
            float2 t3 = make_float2(fs * u3.y, -fs * u3.x);
            int idxD = ((j - jm) << 2) + jm;
            dst[ch][idxD]          = make_float2(t0.x + t2.x, t0.y + t2.y);
            dst[ch][idxD + Ns]     = make_float2(t1.x + t3.x, t1.y + t3.y);
            dst[ch][idxD + 2 * Ns] = make_float2(t0.x - t2.x, t0.y - t2.y);
            dst[ch][idxD + 3 * Ns] = make_float2(t1.x - t3.x, t1.y - t3.y);
        }
        __syncthreads();
        float2 (*tmp)[128] = src; src = dst; dst = tmp;
    }
    for (int i = tid; i < 1024; i += 256) {
        int k1 = i >> 3, ch = i & 7;
        float2 v = src[ch][k1];
        g_bufB[(size_t)(k2 + (k1 << 8)) * 64 + c0 + ch] =
            make_float2(v.x * scale, v.y * scale);
    }
}

// -------------------- FNO core: row DFT + P/M + lin1 + lin2 (2x2 tiled) -----
__global__ __launch_bounds__(256)
void mid_kernel(const float* __restrict__ lin1W, const float* __restrict__ lin1b,
                const float* __restrict__ lin2W, const float* __restrict__ lin2b)
{
    __shared__ float L1t[64 * 65];
    __shared__ float L2t[64 * 65];
    __shared__ float2 zc[16][64];
    __shared__ float2 yc[16][64];
    __shared__ float2 sP[64], sM[64];
    int tid = threadIdx.x;
    int row0 = blockIdx.x << 4;
    for (int i = tid; i < 4096; i += 256) {
        int o = i >> 6, w = i & 63;
        L1t[o * 65 + w] = lin1W[i];
        L2t[o * 65 + w] = lin2W[i];
    }
    if (tid < 64) { sP[tid] = g_P[tid]; sM[tid] = g_M[tid]; }
    for (int i = tid; i < 1024; i += 256) {
        int r = i >> 6, w = i & 63;
        zc[r][w] = g_bufB[(size_t)(row0 + r) * 64 + w];
    }
    __syncthreads();
    const int r0 = (tid >> 5) << 1, r1 = r0 + 1;
    const int w0 = tid & 31, w1 = w0 + 32;
    float a00r = 0, a00i = 0, a01r = 0, a01i = 0;
    float a10r = 0, a10i = 0, a11r = 0, a11i = 0;
#pragma unroll 8
    for (int ww = 0; ww < 64; ww++) {
        float2 z0 = zc[r0][ww], z1 = zc[r1][ww];
        float2 t0 = g_dftF[(ww << 6) + w0], t1 = g_dftF[(ww << 6) + w1];
        a00r += z0.x * t0.x - z0.y * t0.y;  a00i += z0.x * t0.y + z0.y * t0.x;
        a01r += z0.x * t1.x - z0.y * t1.y;  a01i += z0.x * t1.y + z0.y * t1.x;
        a10r += z1.x * t0.x - z1.y * t0.y;  a10i += z1.x * t0.y + z1.y * t0.x;
        a11r += z1.x * t1.x - z1.y * t1.y;  a11i += z1.x * t1.y + z1.y * t1.x;
    }
    {
        float2 P0 = sP[w0], M0 = sM[w0], P1 = sP[w1], M1 = sM[w1];
#define PM(xr, xi, P, Mv, out)                                              \
        {                                                                   \
            float rp = fmaxf(xr, 0.f), rn = fmaxf(-(xr), 0.f);              \
            float ip = fmaxf(xi, 0.f), iq = fmaxf(-(xi), 0.f);              \
            out = make_float2(rp * P.x - ip * P.y + rn * Mv.x - iq * Mv.y,  \
                              rp * P.y + ip * P.x + rn * Mv.y + iq * Mv.x); \
        }
        float2 y00, y01, y10, y11;
        PM(a00r, a00i, P0, M0, y00)
        PM(a01r, a01i, P1, M1, y01)
        PM(a10r, a10i, P0, M0, y10)
        PM(a11r, a11i, P1, M1, y11)
#undef PM
        yc[r0][w0] = y00; yc[r0][w1] = y01;
        yc[r1][w0] = y10; yc[r1][w1] = y11;
    }
    __syncthreads();
    float b0 = lin1b[w0], b1 = lin1b[w1];
    float s00r = b0, s00i = 0, s01r = b1, s01i = 0;
    float s10r = b0, s10i = 0, s11r = b1, s11i = 0;
#pragma unroll 8
    for (int ww = 0; ww < 64; ww++) {
        float2 y0 = yc[r0][ww], y1 = yc[r1][ww];
        float u0 = L1t[w0 * 65 + ww], u1 = L1t[w1 * 65 + ww];
        s00r += u0 * y0.x;  s00i += u0 * y0.y;
        s01r += u1 * y0.x;  s01i += u1 * y0.y;
        s10r += u0 * y1.x;  s10i += u0 * y1.y;
        s11r += u1 * y1.x;  s11i += u1 * y1.y;
    }
    s00r = fmaxf(s00r, 0.f); s00i = fmaxf(s00i, 0.f);
    s01r = fmaxf(s01r, 0.f); s01i = fmaxf(s01i, 0.f);
    s10r = fmaxf(s10r, 0.f); s10i = fmaxf(s10i, 0.f);
    s11r = fmaxf(s11r, 0.f); s11i = fmaxf(s11i, 0.f);
    __syncthreads();
    yc[r0][w0] = make_float2(s00r, s00i);
    yc[r0][w1] = make_float2(s01r, s01i);
    yc[r1][w0] = make_float2(s10r, s10i);
    yc[r1][w1] = make_float2(s11r, s11i);
    __syncthreads();
    b0 = lin2b[w0]; b1 = lin2b[w1];
    s00r = b0; s00i = 0; s01r = b1; s01i = 0;
    s10r = b0; s10i = 0; s11r = b1; s11i = 0;
#pragma unroll 8
    for (int ww = 0; ww < 64; ww++) {
        float2 y0 = yc[r0][ww], y1 = yc[r1][ww];
        float u0 = L2t[w0 * 65 + ww], u1 = L2t[w1 * 65 + ww];
        s00r += u0 * y0.x;  s00i += u0 * y0.y;
        s01r += u1 * y0.x;  s01i += u1 * y0.y;
        s10r += u0 * y1.x;  s10i += u0 * y1.y;
        s11r += u1 * y1.x;  s11i += u1 * y1.y;
    }
    g_bufA[(size_t)(row0 + r0) * 64 + w0] = make_float2(s00r, s00i);
    g_bufA[(size_t)(row0 + r0) * 64 + w1] = make_float2(s01r, s01i);
    g_bufA[(size_t)(row0 + r1) * 64 + w0] = make_float2(s10r, s10i);
    g_bufA[(size_t)(row0 + r1) * 64 + w1] = make_float2(s11r, s11i);
}

// -------------------- inverse row DFT-64 + W_out (2x2 / 2x4 tiled) ----------
__global__ __launch_bounds__(256)
void out_kernel(const float* __restrict__ Wout, const float* __restrict__ bout,
                float* __restrict__ outp, int interleaved)
{
    __shared__ float Wt[128 * 65];
    __shared__ float2 zc[16][64];
    __shared__ float2 su[16][64];
    int tid = threadIdx.x;
    int row0 = blockIdx.x << 4;
    for (int i = tid; i < 8192; i += 256) {
        int f = i >> 6, w = i & 63;
        Wt[f * 65 + w] = Wout[i];
    }
    for (int i = tid; i < 1024; i += 256) {
        int r = i >> 6, w = i & 63;
        zc[r][w] = g_bufB[(size_t)(row0 + r) * 64 + w];
    }
    __syncthreads();
    const int r0 = (tid >> 5) << 1, r1 = r0 + 1;
    const int w0 = tid & 31, w1 = w0 + 32;
    float a00r = 0, a00i = 0, a01r = 0, a01i = 0;
    float a10r = 0, a10i = 0, a11r = 0, a11i = 0;
#pragma unroll 8
    for (int k = 0; k < 64; k++) {
        float2 z0 = zc[r0][k], z1 = zc[r1][k];
        float2 t0 = g_dftI[(k << 6) + w0], t1 = g_dftI[(k << 6) + w1];
        a00r += z0.x * t0.x - z0.y * t0.y;  a00i += z0.x * t0.y + z0.y * t0.x;
        a01r += z0.x * t1.x - z0.y * t1.y;  a01i += z0.x * t1.y + z0.y * t1.x;
        a10r += z1.x * t0.x - z1.y * t0.y;  a10i += z1.x * t0.y + z1.y * t0.x;
        a11r += z1.x * t1.x - z1.y * t1.y;  a11i += z1.x * t1.y + z1.y * t1.x;
    }
    su[r0][w0] = make_float2(a00r, a00i);
    su[r0][w1] = make_float2(a01r, a01i);
    su[r1][w0] = make_float2(a10r, a10i);
    su[r1][w1] = make_float2(a11r, a11i);
    __syncthreads();
    const int f0 = tid & 31;
    float p[2][4][2];
#pragma unroll
    for (int a = 0; a < 2; a++)
#pragma unroll
        for (int b = 0; b < 4; b++) {
            p[a][b][0] = bout[f0 + 32 * b];
            p[a][b][1] = 0.f;
        }
#pragma unroll 8
    for (int w = 0; w < 64; w++) {
        float2 u0 = su[r0][w], u1 = su[r1][w];
        float w0v = Wt[(f0)      * 65 + w];
        float w1v = Wt[(f0 + 32) * 65 + w];
        float w2v = Wt[(f0 + 64) * 65 + w];
        float w3v = Wt[(f0 + 96) * 65 + w];
        p[0][0][0] += w0v * u0.x;  p[0][0][1] += w0v * u0.y;
        p[0][1][0] += w1v * u0.x;  p[0][1][1] += w1v * u0.y;
        p[0][2][0] += w2v * u0.x;  p[0][2][1] += w2v * u0.y;
        p[0][3][0] += w3v * u0.x;  p[0][3][1] += w3v * u0.y;
        p[1][0][0] += w0v * u1.x;  p[1][0][1] += w0v * u1.y;
        p[1][1][0] += w1v * u1.x;  p[1][1][1] += w1v * u1.y;
        p[1][2][0] += w2v * u1.x;  p[1][2][1] += w2v * u1.y;
        p[1][3][0] += w3v * u1.x;  p[1][3][1] += w3v * u1.y;
    }
#pragma unroll
    for (int a = 0; a < 2; a++) {
        int row = row0 + (a == 0 ? r0 : r1);
#pragma unroll
        for (int b = 0; b < 4; b++) {
            size_t oidx = (size_t)row * 128 + f0 + 32 * b;
            if (interleaved) {
                reinterpret_cast<float2*>(outp)[oidx] = make_float2(p[a][b][0], p[a][b][1]);
            } else {
                outp[oidx] = p[a][b][0];
            }
        }
    }
}

// ---------------------------------------------------------------------------
extern "C" void kernel_launch(void* const* d_in, const int* in_sizes, int n_in,
                              void* d_out, int out_size)
{
    (void)in_sizes; (void)n_in;
    const float* geom  = (const float*)d_in[0];
    const float* W_in  = (const float*)d_in[1];
    const float* b_in  = (const float*)d_in[2];
    const float* W_h1  = (const float*)d_in[3];
    const float* b_h1  = (const float*)d_in[4];
    const float* W_h2  = (const float*)d_in[5];
    const float* b_h2  = (const float*)d_in[6];
    const float* w0    = (const float*)d_in[7];
    const float* w1    = (const float*)d_in[8];
    const float* lin1W = (const float*)d_in[9];
    const float* lin1b = (const float*)d_in[10];
    const float* lin2W = (const float*)d_in[11];
    const float* lin2b = (const float*)d_in[12];
    const float* Wout  = (const float*)d_in[13];
    const float* bout  = (const float*)d_in[14];

    const int GSM128 = 3 * 8192 + 3 * 128 * 64;   // 49152 bytes
    const int GSM64  = 3 * 8192 + 3 * 64 * 64;    // 36864 bytes
    cudaFuncSetAttribute(mma_gemm<128, 0>, cudaFuncAttributeMaxDynamicSharedMemorySize, GSM128);
    cudaFuncSetAttribute(mma_gemm<128, 1>, cudaFuncAttributeMaxDynamicSharedMemorySize, GSM128);
    cudaFuncSetAttribute(mma_gemm<64, 2>,  cudaFuncAttributeMaxDynamicSharedMemorySize, GSM64);

    // mma_gemm<128,1> (GEMM2) stays in the 4th-launch ncu capture slot
    split_geom<<<(NB * 512 / 4) / 256, 256>>>(geom, NB * 512 / 4);
    split_w<0><<<2 * (1024 * 512 / 4) / 256, 256>>>(W_in, W_h1, 1024 * 512 / 4);
    mma_gemm<128, 0><<<dim3(1024 / 128, NB / 128), 256, GSM128>>>(b_in, NB, 1024, 512);
    mma_gemm<128, 1><<<dim3(512 / 128, NB / 128), 256, GSM128>>>(b_h1, NB, 512, 1024);
    init_tables<<<64, 256>>>(w0, w1);
    split_w<1><<<(64 * 512 / 4) / 256, 256>>>(W_h2, nullptr, 64 * 512 / 4);
    mma_gemm<64, 2><<<dim3(1, NB / 128), 256, GSM64>>>(b_h2, NB, 64, 512);

    // forward batch FFT directly on real g_xr
    fft_b_step1<1><<<dim3(128, 8), 256>>>(1.f);
    fft_b_step2<<<dim3(256, 8), 256>>>(1.f, 1.0f);

    // FNO core: row DFT + P/M + lin1 + lin2
    mid_kernel<<<NB / 16, 256>>>(lin1W, lin1b, lin2W, lin2b);

    // inverse batch FFT (conjugated twiddles)
    fft_b_step1<0><<<dim3(128, 8), 256>>>(-1.f);
    fft_b_step2<<<dim3(256, 8), 256>>>(-1.f, 1.0f / 32768.0f);

    // inverse row DFT-64 + output projection
    int interleaved = (out_size >= 2 * NB * 128) ? 1 : 0;
    out_kernel<<<NB / 16, 256>>>(Wout, bout, (float*)d_out, interleaved);
}